// round 8
// baseline (speedup 1.0000x reference)
#include <cuda_runtime.h>
#include <math.h>

#define BATCH 2048
#define TT    2048
#define HH    25
#define NPAIR 13

typedef unsigned long long u64;

// Packed f32x2 ops (Blackwell, PTX-only). Two fp32 FMAs/MULs per instruction.
__device__ __forceinline__ u64 ffma2(u64 a, u64 b, u64 c) {
    u64 d; asm("fma.rn.f32x2 %0, %1, %2, %3;" : "=l"(d) : "l"(a), "l"(b), "l"(c)); return d;
}
__device__ __forceinline__ u64 fmul2(u64 a, u64 b) {
    u64 d; asm("mul.rn.f32x2 %0, %1, %2;" : "=l"(d) : "l"(a), "l"(b)); return d;
}
__device__ __forceinline__ u64 pk2(float lo, float hi) {
    u64 r; asm("mov.b64 %0, {%1, %2};" : "=l"(r) : "f"(lo), "f"(hi)); return r;
}
__device__ __forceinline__ float lo2(u64 a) { return __uint_as_float((unsigned)a); }
__device__ __forceinline__ float hi2(u64 a) { return __uint_as_float((unsigned)(a >> 32)); }

__device__ __forceinline__ float ex2a(float x) { float r; asm("ex2.approx.f32 %0, %1;" : "=f"(r) : "f"(x)); return r; }
__device__ __forceinline__ float rcpa(float x) { float r; asm("rcp.approx.f32 %0, %1;" : "=f"(r) : "f"(x)); return r; }

__device__ __forceinline__ u64 lds64(unsigned a) {
    u64 r; asm volatile("ld.shared.b64 %0, [%1];" : "=l"(r) : "r"(a) : "memory"); return r;
}
__device__ __forceinline__ float ldsf32(unsigned a) {
    float r; asm volatile("ld.shared.f32 %0, [%1];" : "=f"(r) : "r"(a) : "memory"); return r;
}
__device__ __forceinline__ void sts64(unsigned a, u64 v) {
    asm volatile("st.shared.b64 [%0], %1;" :: "r"(a), "l"(v) : "memory");
}
__device__ __forceinline__ void sts32(unsigned a, float v) {
    asm volatile("st.shared.f32 [%0], %1;" :: "r"(a), "f"(v) : "memory");
}
__device__ __forceinline__ void barsync() {
    asm volatile("bar.sync 0, 64;" ::: "memory");
}

#define LOG2E 1.44269504088896340736f
__device__ __forceinline__ float sig_f(float x)  { return rcpa(1.0f + ex2a(-LOG2E * x)); }
__device__ __forceinline__ float tanh_f(float x) { return fmaf(2.0f, rcpa(1.0f + ex2a(-2.0f * LOG2E * x)), -1.0f); }

// Warp-specialized LSTM: ONE sequence per 64-thread CTA, 2 cooperating warps.
//   Warp A (wid 0): raw pre-activation dots for gates i,f (no activations),
//     published packed via STS.64; plus the dense head (butterfly on h[t-1],
//     off the critical path) stored one step delayed.
//   Warp B (wid 1): dots for g,o + their activations; after bar2 consumes A's
//     dots, applies x-projection + sigmoids for i,f, updates c and h,
//     publishes h for the next step.
// Single h broadcast buffer (slot 25 = permanent 1.0 feeding the bias packed
// into each gate's pair-12 hi slot); two bar.syncs per step make ping-pong
// unnecessary. Doubles warps/SM (28) vs previous rounds to fix latency-hiding
// starvation, and halves per-warp instructions.
__global__ void __launch_bounds__(64, 14)
lstm_ws(const float* __restrict__ x,        // [B, T, 1]
        const float* __restrict__ w_ih,     // [4H, 1]
        const float* __restrict__ w_hh,     // [4H, H]
        const float* __restrict__ b_ih,     // [4H]
        const float* __restrict__ b_hh,     // [4H]
        const float* __restrict__ w_dense,  // [1, H]
        const float* __restrict__ b_dense,  // [1]
        float* __restrict__ out)            // [B, T, 1]
{
    __shared__ __align__(16) float sm[96];   // [0..31] h + const1, [32..95] if-dots (32 u64)

    const int lane = (int)(threadIdx.x & 31u);
    const int wid  = (int)(threadIdx.x >> 5);
    const int seq  = blockIdx.x;
    const int j = (lane < HH) ? lane : (HH - 1);

    // Each warp owns 2 gates: A -> {0:i, 1:f}, B -> {2:g, 3:o}.
    const int g0 = 2 * wid, g1 = 2 * wid + 1;
    u64 W0[NPAIR], W1[NPAIR];
    {
        const float* r0 = w_hh + (g0 * HH + j) * HH;
        const float* r1 = w_hh + (g1 * HH + j) * HH;
#pragma unroll
        for (int p = 0; p < NPAIR - 1; p++) {
            W0[p] = pk2(r0[2 * p], r0[2 * p + 1]);
            W1[p] = pk2(r1[2 * p], r1[2 * p + 1]);
        }
        W0[NPAIR - 1] = pk2(r0[24], b_ih[g0 * HH + j] + b_hh[g0 * HH + j]);
        W1[NPAIR - 1] = pk2(r1[24], b_ih[g1 * HH + j] + b_hh[g1 * HH + j]);
    }

    const unsigned ah  = (unsigned)__cvta_generic_to_shared(sm);
    const unsigned aif = ah + 128u;            // u64 if-dot slots
    const unsigned sifl = aif + 8u * (unsigned)lane;

    if (wid == 0) sm[lane] = (lane == HH) ? 1.0f : 0.0f;  // h=0, slot25=1, 26..31=0
    barsync();

    if (wid == 0) {
        // ================= Warp A: i,f dots + dense head =================
        const float wd = (lane < HH) ? w_dense[lane] : 0.0f;
        const float bd = b_dense[0];
        float* orow = out + (size_t)seq * TT;
        const unsigned shl = ah + 4u * (unsigned)lane;

#pragma unroll 1
        for (int t = 0; t < TT; ++t) {
            u64 h0 = lds64(ah);
            u64 a0 = fmul2(h0, W0[0]);
            u64 a1 = fmul2(h0, W1[0]);
#pragma unroll
            for (int p = 1; p < NPAIR; ++p) {
                const u64 hpv = lds64(ah + 8u * p);
                a0 = ffma2(hpv, W0[p], a0);
                a1 = ffma2(hpv, W1[p], a1);
            }
            const float di = lo2(a0) + hi2(a0);   // raw i-dot (incl. bias)
            const float df = lo2(a1) + hi2(a1);   // raw f-dot (incl. bias)
            sts64(sifl, pk2(di, df));
            float hl = ldsf32(shl);               // h[t-1][lane]
            float pr = hl * wd;                   // forces hl completion pre-bar
            barsync();                            // bar2: dots visible to B
            // dense head for h[t-1], fully overlapped with B's tail
            pr += __shfl_xor_sync(0xffffffffu, pr, 16);
            pr += __shfl_xor_sync(0xffffffffu, pr, 8);
            pr += __shfl_xor_sync(0xffffffffu, pr, 4);
            pr += __shfl_xor_sync(0xffffffffu, pr, 2);
            pr += __shfl_xor_sync(0xffffffffu, pr, 1);
            if (lane == 0 && t) orow[t - 1] = pr + bd;   // y[t-1], delayed
            barsync();                            // bar1: B's h(t) published
        }
        // final y[T-1] (h buffer now holds h[T-1])
        float hl = ldsf32(shl);
        float pr = hl * wd;
        pr += __shfl_xor_sync(0xffffffffu, pr, 16);
        pr += __shfl_xor_sync(0xffffffffu, pr, 8);
        pr += __shfl_xor_sync(0xffffffffu, pr, 4);
        pr += __shfl_xor_sync(0xffffffffu, pr, 2);
        pr += __shfl_xor_sync(0xffffffffu, pr, 1);
        if (lane == 0) orow[TT - 1] = pr + bd;
    } else {
        // ================= Warp B: g,o + nonlinear + state =================
        const float ui = w_ih[0 * HH + j], uf = w_ih[1 * HH + j];
        const float ug = w_ih[2 * HH + j], uo = w_ih[3 * HH + j];
        const float2* xp = reinterpret_cast<const float2*>(x + (size_t)seq * TT);
        const unsigned sh = ah + 4u * (unsigned)lane;
        float c = 0.0f;
        float2 xq = xp[0];

#define BSTEP(XV)                                                             \
        {                                                                     \
            u64 h0 = lds64(ah);                                               \
            u64 a0 = fmul2(h0, W0[0]);   /* g */                              \
            u64 a1 = fmul2(h0, W1[0]);   /* o */                              \
            _Pragma("unroll")                                                 \
            for (int p = 1; p < NPAIR; ++p) {                                 \
                const u64 hpv = lds64(ah + 8u * p);                           \
                a0 = ffma2(hpv, W0[p], a0);                                   \
                a1 = ffma2(hpv, W1[p], a1);                                   \
            }                                                                 \
            const float pg = fmaf((XV), ug, lo2(a0) + hi2(a0));               \
            const float po = fmaf((XV), uo, lo2(a1) + hi2(a1));               \
            const float gg = tanh_f(pg);                                      \
            const float go = sig_f(po);                                       \
            barsync();                            /* bar2: A's dots ready */  \
            const u64 dif = lds64(sifl);                                      \
            const float gi = sig_f(fmaf((XV), ui, lo2(dif)));                 \
            const float gf = sig_f(fmaf((XV), uf, hi2(dif)));                 \
            c = fmaf(gf, c, gi * gg);                                         \
            const float hv = go * tanh_f(c);                                  \
            if (lane < HH) sts32(sh, hv);                                     \
            barsync();                            /* bar1: h(t) published */  \
        }

#pragma unroll 1
        for (int tb = 0; tb < TT / 2; ++tb) {
            float2 xn = xp[(tb + 1 < TT / 2) ? tb + 1 : tb];   // prefetch
            BSTEP(xq.x)
            BSTEP(xq.y)
            xq = xn;
        }
#undef BSTEP
    }
}

extern "C" void kernel_launch(void* const* d_in, const int* in_sizes, int n_in,
                              void* d_out, int out_size) {
    const float* x       = (const float*)d_in[0];
    const float* w_ih    = (const float*)d_in[1];
    const float* w_hh    = (const float*)d_in[2];
    const float* b_ih    = (const float*)d_in[3];
    const float* b_hh    = (const float*)d_in[4];
    const float* w_dense = (const float*)d_in[5];
    const float* b_dense = (const float*)d_in[6];
    float* out = (float*)d_out;

    // 2048 CTAs x 64 threads: one sequence per CTA, 2 specialized warps.
    // 14 CTAs/SM (reg cap 72) -> 28 warps/SM, single wave across 148 SMs.
    lstm_ws<<<BATCH, 64>>>(x, w_ih, w_hh, b_ih, b_hh, w_dense, b_dense, out);
}

// round 9
// speedup vs baseline: 1.1857x; 1.1857x over previous
#include <cuda_runtime.h>
#include <math.h>

#define BATCH 2048
#define TT    2048
#define HH    25
#define NPAIR 13

typedef unsigned long long u64;

// Packed f32x2 ops (Blackwell, PTX-only): two fp32 FMAs/MULs per instruction,
// measured to occupy the FMA pipe like ONE scalar FFMA (rt=2) -> true 2x FLOPs.
__device__ __forceinline__ u64 ffma2(u64 a, u64 b, u64 c) {
    u64 d; asm("fma.rn.f32x2 %0, %1, %2, %3;" : "=l"(d) : "l"(a), "l"(b), "l"(c)); return d;
}
__device__ __forceinline__ u64 fmul2(u64 a, u64 b) {
    u64 d; asm("mul.rn.f32x2 %0, %1, %2;" : "=l"(d) : "l"(a), "l"(b)); return d;
}
__device__ __forceinline__ u64 pk2(float lo, float hi) {
    u64 r; asm("mov.b64 %0, {%1, %2};" : "=l"(r) : "f"(lo), "f"(hi)); return r;
}
__device__ __forceinline__ float lo2(u64 a) { return __uint_as_float((unsigned)a); }
__device__ __forceinline__ float hi2(u64 a) { return __uint_as_float((unsigned)(a >> 32)); }

__device__ __forceinline__ float ex2a(float x) { float r; asm("ex2.approx.f32 %0, %1;" : "=f"(r) : "f"(x)); return r; }
__device__ __forceinline__ float rcpa(float x) { float r; asm("rcp.approx.f32 %0, %1;" : "=f"(r) : "f"(x)); return r; }

__device__ __forceinline__ u64 lds64(unsigned a) {
    u64 r; asm volatile("ld.shared.b64 %0, [%1];" : "=l"(r) : "r"(a) : "memory"); return r;
}
__device__ __forceinline__ void sts32(unsigned a, float v) {
    asm volatile("st.shared.f32 [%0], %1;" :: "r"(a), "f"(v) : "memory");
}

#define LOG2E 1.44269504088896340736f
__device__ __forceinline__ float sig_f(float x)  { return rcpa(1.0f + ex2a(-LOG2E * x)); }
__device__ __forceinline__ float tanh_f(float x) { return fmaf(2.0f, rcpa(1.0f + ex2a(-2.0f * LOG2E * x)), -1.0f); }

// TWO sequences per warp, sharing one register-resident weight set (weights are
// sequence-invariant). Lane j owns hidden unit j of BOTH sequences. Per step,
// per sequence: 13 broadcast LDS.64 of packed h pairs, 5 packed dot products
// (4 gates + dense head) off the same loads, activations, STS.32 of h.
// The dense head is a matvec against a replicated w_dense row (bias via the
// pair-12 hi slot x const-1.0 shared slot 25) -> NO shuffles anywhere; it
// yields y[t-1] each step (h[t-1] is what's being broadcast), stored delayed,
// with one extra broadcast round after the loop for y[T-1].
// Two independent recurrence chains per warp double issue eligibility; no
// inter-warp synchronization at all (one warp per 32-thread CTA).
__global__ void __launch_bounds__(32, 7)
lstm_x2(const float* __restrict__ x,        // [B, T, 1]
        const float* __restrict__ w_ih,     // [4H, 1]
        const float* __restrict__ w_hh,     // [4H, H]
        const float* __restrict__ b_ih,     // [4H]
        const float* __restrict__ b_hh,     // [4H]
        const float* __restrict__ w_dense,  // [1, H]
        const float* __restrict__ b_dense,  // [1]
        float* __restrict__ out)            // [B, T, 1]
{
    __shared__ __align__(16) float hb[2][2][32];   // [ping][seq][slot]

    const int lane = (int)(threadIdx.x & 31u);
    const int j = (lane < HH) ? lane : (HH - 1);
    const int seqA = blockIdx.x * 2;               // two sequences per warp

    // ---- shared weight set: 4 gates x 13 packed pairs + dense row ----
    u64 W[4][NPAIR], Wd[NPAIR];
#pragma unroll
    for (int g = 0; g < 4; g++) {
        const float* row = w_hh + (g * HH + j) * HH;
#pragma unroll
        for (int p = 0; p < NPAIR - 1; p++)
            W[g][p] = pk2(row[2 * p], row[2 * p + 1]);
        W[g][NPAIR - 1] = pk2(row[24], b_ih[g * HH + j] + b_hh[g * HH + j]);
    }
#pragma unroll
    for (int p = 0; p < NPAIR - 1; p++)
        Wd[p] = pk2(w_dense[2 * p], w_dense[2 * p + 1]);
    Wd[NPAIR - 1] = pk2(w_dense[24], b_dense[0]);   // bias in hi slot

    const float ui = w_ih[0 * HH + j], uf = w_ih[1 * HH + j];
    const float ug = w_ih[2 * HH + j], uo = w_ih[3 * HH + j];

    const float2* xpA = reinterpret_cast<const float2*>(x + (size_t)seqA * TT);
    const float2* xpB = reinterpret_cast<const float2*>(x + (size_t)(seqA + 1) * TT);
    float* oA = out + (size_t)seqA * TT;
    float* oB = out + (size_t)(seqA + 1) * TT;

    const unsigned base = (unsigned)__cvta_generic_to_shared(&hb[0][0][0]);
    const unsigned aP0A = base,        aP0B = base + 128u;
    const unsigned aP1A = base + 256u, aP1B = base + 384u;
    const unsigned sl = 4u * (unsigned)lane;

    // init all 4 buffers: h=0, slot 25 = 1.0 (permanent bias feed), 26..31 = 0
    {
        const float v = (lane == HH) ? 1.0f : 0.0f;
        hb[0][0][lane] = v; hb[0][1][lane] = v;
        hb[1][0][lane] = v; hb[1][1][lane] = v;
    }
    __syncwarp();

    float cA = 0.0f, cB = 0.0f;
    float2 xqA = xpA[0], xqB = xpB[0];

    // One step for both sequences. RA_/WA_ are literal ping-pong addresses.
    // STORE0: whether the delayed y[t-1] store is live (false only at t=0).
#define STEP(RA_A, RA_B, WA_A, WA_B, XA, XB, STORE0, GT)                      \
    {                                                                         \
        u64 hA0 = lds64(RA_A);                                                \
        u64 hB0 = lds64(RA_B);                                                \
        u64 iA = fmul2(hA0, W[0][0]), fA = fmul2(hA0, W[1][0]);               \
        u64 gA = fmul2(hA0, W[2][0]), oAc = fmul2(hA0, W[3][0]);              \
        u64 dA = fmul2(hA0, Wd[0]);                                           \
        u64 iB = fmul2(hB0, W[0][0]), fB = fmul2(hB0, W[1][0]);               \
        u64 gB = fmul2(hB0, W[2][0]), oBc = fmul2(hB0, W[3][0]);              \
        u64 dB = fmul2(hB0, Wd[0]);                                           \
        _Pragma("unroll")                                                     \
        for (int p = 1; p < NPAIR; p++) {                                     \
            const u64 pa = lds64((RA_A) + 8u * p);                            \
            const u64 pb = lds64((RA_B) + 8u * p);                            \
            iA = ffma2(pa, W[0][p], iA);  iB = ffma2(pb, W[0][p], iB);        \
            fA = ffma2(pa, W[1][p], fA);  fB = ffma2(pb, W[1][p], fB);        \
            gA = ffma2(pa, W[2][p], gA);  gB = ffma2(pb, W[2][p], gB);        \
            oAc = ffma2(pa, W[3][p], oAc); oBc = ffma2(pb, W[3][p], oBc);     \
            dA = ffma2(pa, Wd[p], dA);    dB = ffma2(pb, Wd[p], dB);          \
        }                                                                     \
        /* dense head = y[t-1] (broadcast h is h[t-1]); bias already inside */\
        if ((STORE0) && lane == 0) {                                          \
            oA[(GT) - 1] = lo2(dA) + hi2(dA);                                 \
            oB[(GT) - 1] = lo2(dB) + hi2(dB);                                 \
        }                                                                     \
        const float piA = fmaf((XA), ui, lo2(iA) + hi2(iA));                  \
        const float pfA = fmaf((XA), uf, lo2(fA) + hi2(fA));                  \
        const float pgA = fmaf((XA), ug, lo2(gA) + hi2(gA));                  \
        const float poA = fmaf((XA), uo, lo2(oAc) + hi2(oAc));                \
        const float piB = fmaf((XB), ui, lo2(iB) + hi2(iB));                  \
        const float pfB = fmaf((XB), uf, lo2(fB) + hi2(fB));                  \
        const float pgB = fmaf((XB), ug, lo2(gB) + hi2(gB));                  \
        const float poB = fmaf((XB), uo, lo2(oBc) + hi2(oBc));                \
        const float giA = sig_f(piA), gfA = sig_f(pfA);                       \
        const float ggA = tanh_f(pgA), goA = sig_f(poA);                      \
        const float giB = sig_f(piB), gfB = sig_f(pfB);                       \
        const float ggB = tanh_f(pgB), goB = sig_f(poB);                      \
        cA = fmaf(gfA, cA, giA * ggA);                                        \
        cB = fmaf(gfB, cB, giB * ggB);                                        \
        const float hvA = goA * tanh_f(cA);                                   \
        const float hvB = goB * tanh_f(cB);                                   \
        if (lane < HH) { sts32((WA_A) + sl, hvA); sts32((WA_B) + sl, hvB); }  \
        __syncwarp();                                                         \
    }

#pragma unroll 1
    for (int tb = 0; tb < TT / 2; tb++) {
        const int tn = (tb + 1 < TT / 2) ? tb + 1 : tb;
        float2 xnA = xpA[tn], xnB = xpB[tn];            // prefetch next block
        STEP(aP0A, aP0B, aP1A, aP1B, xqA.x, xqB.x, (tb > 0), 2 * tb)
        STEP(aP1A, aP1B, aP0A, aP0B, xqA.y, xqB.y, true,     2 * tb + 1)
        xqA = xnA; xqB = xnB;
    }
#undef STEP

    // tail: one more broadcast round for y[T-1] (final h is in ping 0)
    {
        u64 dA = fmul2(lds64(aP0A), Wd[0]);
        u64 dB = fmul2(lds64(aP0B), Wd[0]);
#pragma unroll
        for (int p = 1; p < NPAIR; p++) {
            dA = ffma2(lds64(aP0A + 8u * p), Wd[p], dA);
            dB = ffma2(lds64(aP0B + 8u * p), Wd[p], dB);
        }
        if (lane == 0) {
            oA[TT - 1] = lo2(dA) + hi2(dA);
            oB[TT - 1] = lo2(dB) + hi2(dB);
        }
    }
}

extern "C" void kernel_launch(void* const* d_in, const int* in_sizes, int n_in,
                              void* d_out, int out_size) {
    const float* x       = (const float*)d_in[0];
    const float* w_ih    = (const float*)d_in[1];
    const float* w_hh    = (const float*)d_in[2];
    const float* b_ih    = (const float*)d_in[3];
    const float* b_hh    = (const float*)d_in[4];
    const float* w_dense = (const float*)d_in[5];
    const float* b_dense = (const float*)d_in[6];
    float* out = (float*)d_out;

    // 1024 CTAs x 32 threads: one warp per CTA, two sequences per warp.
    // 7 CTAs/SM (reg cap ~255, no pressure) -> near-perfect single wave:
    // 136 SMs x 7 warps + 12 x 6.
    lstm_x2<<<BATCH / 2, 32>>>(x, w_ih, w_hh, b_ih, b_hh,
                               w_dense, b_dense, out);
}

// round 10
// speedup vs baseline: 1.1959x; 1.0086x over previous
#include <cuda_runtime.h>
#include <math.h>

#define BATCH 2048
#define TT    2048
#define HH    25
#define NPAIR 13

typedef unsigned long long u64;

// Packed f32x2 ops (Blackwell, PTX-only): two fp32 FMAs/MULs per instruction.
__device__ __forceinline__ u64 ffma2(u64 a, u64 b, u64 c) {
    u64 d; asm("fma.rn.f32x2 %0, %1, %2, %3;" : "=l"(d) : "l"(a), "l"(b), "l"(c)); return d;
}
__device__ __forceinline__ u64 fmul2(u64 a, u64 b) {
    u64 d; asm("mul.rn.f32x2 %0, %1, %2;" : "=l"(d) : "l"(a), "l"(b)); return d;
}
__device__ __forceinline__ u64 pk2(float lo, float hi) {
    u64 r; asm("mov.b64 %0, {%1, %2};" : "=l"(r) : "f"(lo), "f"(hi)); return r;
}
__device__ __forceinline__ float lo2(u64 a) { return __uint_as_float((unsigned)a); }
__device__ __forceinline__ float hi2(u64 a) { return __uint_as_float((unsigned)(a >> 32)); }

__device__ __forceinline__ float ex2a(float x) { float r; asm("ex2.approx.f32 %0, %1;" : "=f"(r) : "f"(x)); return r; }
__device__ __forceinline__ float rcpa(float x) { float r; asm("rcp.approx.f32 %0, %1;" : "=f"(r) : "f"(x)); return r; }

__device__ __forceinline__ u64 lds64(unsigned a) {
    u64 r; asm volatile("ld.shared.b64 %0, [%1];" : "=l"(r) : "r"(a) : "memory"); return r;
}
__device__ __forceinline__ void sts32(unsigned a, float v) {
    asm volatile("st.shared.f32 [%0], %1;" :: "r"(a), "f"(v) : "memory");
}

#define LOG2E 1.44269504088896340736f

// TWO sequences per warp sharing one register-resident weight set. Lane j owns
// hidden unit j of both sequences. Per step/seq: 13 broadcast LDS.64 of packed
// h pairs, 5 packed dots (4 gates + dense head, bias via pair-12 hi slot x
// const-1.0 shared slot 25), batched activations, STS.32 of h.
// Round-10 deltas vs R9 (numerics identical):
//  - NO __syncwarp: smem is warp-private, asm-volatile ops pin compiler order,
//    and the per-warp in-order LSU orders STS before the next step's LDS;
//    ping-pong buffers remove WAR hazards. Unfences cross-step scheduling.
//  - Activation MUFUs batched: all 8 ex2 (both seqs) issued back-to-back so
//    they pipeline at rt=8 instead of chaining 16-cycle latencies.
__global__ void __launch_bounds__(32, 7)
lstm_x2(const float* __restrict__ x,        // [B, T, 1]
        const float* __restrict__ w_ih,     // [4H, 1]
        const float* __restrict__ w_hh,     // [4H, H]
        const float* __restrict__ b_ih,     // [4H]
        const float* __restrict__ b_hh,     // [4H]
        const float* __restrict__ w_dense,  // [1, H]
        const float* __restrict__ b_dense,  // [1]
        float* __restrict__ out)            // [B, T, 1]
{
    __shared__ __align__(16) float hb[2][2][32];   // [ping][seq][slot]

    const int lane = (int)(threadIdx.x & 31u);
    const int j = (lane < HH) ? lane : (HH - 1);
    const int seqA = blockIdx.x * 2;

    // ---- shared weight set: 4 gates x 13 packed pairs + dense row ----
    u64 W[4][NPAIR], Wd[NPAIR];
#pragma unroll
    for (int g = 0; g < 4; g++) {
        const float* row = w_hh + (g * HH + j) * HH;
#pragma unroll
        for (int p = 0; p < NPAIR - 1; p++)
            W[g][p] = pk2(row[2 * p], row[2 * p + 1]);
        W[g][NPAIR - 1] = pk2(row[24], b_ih[g * HH + j] + b_hh[g * HH + j]);
    }
#pragma unroll
    for (int p = 0; p < NPAIR - 1; p++)
        Wd[p] = pk2(w_dense[2 * p], w_dense[2 * p + 1]);
    Wd[NPAIR - 1] = pk2(w_dense[24], b_dense[0]);   // bias in hi slot

    const float ui = w_ih[0 * HH + j], uf = w_ih[1 * HH + j];
    const float ug = w_ih[2 * HH + j], uo = w_ih[3 * HH + j];

    const float2* xpA = reinterpret_cast<const float2*>(x + (size_t)seqA * TT);
    const float2* xpB = reinterpret_cast<const float2*>(x + (size_t)(seqA + 1) * TT);
    float* oA = out + (size_t)seqA * TT;
    float* oB = out + (size_t)(seqA + 1) * TT;

    const unsigned base = (unsigned)__cvta_generic_to_shared(&hb[0][0][0]);
    const unsigned aP0A = base,        aP0B = base + 128u;
    const unsigned aP1A = base + 256u, aP1B = base + 384u;
    const unsigned sl = 4u * (unsigned)lane;

    {
        const float v = (lane == HH) ? 1.0f : 0.0f;
        hb[0][0][lane] = v; hb[0][1][lane] = v;
        hb[1][0][lane] = v; hb[1][1][lane] = v;
    }
    __syncwarp();   // one-time: init visible before the loop

#define NEG1  (-LOG2E)
#define NEG2  (-2.0f * LOG2E)

    float cA = 0.0f, cB = 0.0f;
    float2 xqA = xpA[0], xqB = xpB[0];

#define STEP(RA_A, RA_B, WA_A, WA_B, XA, XB, STORE0, GT)                      \
    {                                                                         \
        u64 hA0 = lds64(RA_A);                                                \
        u64 hB0 = lds64(RA_B);                                                \
        u64 iA = fmul2(hA0, W[0][0]), fA = fmul2(hA0, W[1][0]);               \
        u64 gA = fmul2(hA0, W[2][0]), oAc = fmul2(hA0, W[3][0]);              \
        u64 dA = fmul2(hA0, Wd[0]);                                           \
        u64 iB = fmul2(hB0, W[0][0]), fB = fmul2(hB0, W[1][0]);               \
        u64 gB = fmul2(hB0, W[2][0]), oBc = fmul2(hB0, W[3][0]);              \
        u64 dB = fmul2(hB0, Wd[0]);                                           \
        _Pragma("unroll")                                                     \
        for (int p = 1; p < NPAIR; p++) {                                     \
            const u64 pa = lds64((RA_A) + 8u * p);                            \
            const u64 pb = lds64((RA_B) + 8u * p);                            \
            iA = ffma2(pa, W[0][p], iA);  iB = ffma2(pb, W[0][p], iB);        \
            fA = ffma2(pa, W[1][p], fA);  fB = ffma2(pb, W[1][p], fB);        \
            gA = ffma2(pa, W[2][p], gA);  gB = ffma2(pb, W[2][p], gB);        \
            oAc = ffma2(pa, W[3][p], oAc); oBc = ffma2(pb, W[3][p], oBc);     \
            dA = ffma2(pa, Wd[p], dA);    dB = ffma2(pb, Wd[p], dB);          \
        }                                                                     \
        if ((STORE0) && lane == 0) {                                          \
            oA[(GT) - 1] = lo2(dA) + hi2(dA);                                 \
            oB[(GT) - 1] = lo2(dB) + hi2(dB);                                 \
        }                                                                     \
        /* ---- batched activations: args, then 8 pipelined ex2, adds, rcp */ \
        const float mAi = NEG1 * fmaf((XA), ui, lo2(iA) + hi2(iA));           \
        const float mAf = NEG1 * fmaf((XA), uf, lo2(fA) + hi2(fA));           \
        const float mAg = NEG2 * fmaf((XA), ug, lo2(gA) + hi2(gA));           \
        const float mAo = NEG1 * fmaf((XA), uo, lo2(oAc) + hi2(oAc));         \
        const float mBi = NEG1 * fmaf((XB), ui, lo2(iB) + hi2(iB));           \
        const float mBf = NEG1 * fmaf((XB), uf, lo2(fB) + hi2(fB));           \
        const float mBg = NEG2 * fmaf((XB), ug, lo2(gB) + hi2(gB));           \
        const float mBo = NEG1 * fmaf((XB), uo, lo2(oBc) + hi2(oBc));         \
        const float eAi = ex2a(mAi), eAf = ex2a(mAf);                         \
        const float eAg = ex2a(mAg), eAo = ex2a(mAo);                         \
        const float eBi = ex2a(mBi), eBf = ex2a(mBf);                         \
        const float eBg = ex2a(mBg), eBo = ex2a(mBo);                         \
        const float giA = rcpa(1.0f + eAi), gfA = rcpa(1.0f + eAf);           \
        const float goA = rcpa(1.0f + eAo);                                   \
        const float ggA = fmaf(2.0f, rcpa(1.0f + eAg), -1.0f);                \
        const float giB = rcpa(1.0f + eBi), gfB = rcpa(1.0f + eBf);           \
        const float goB = rcpa(1.0f + eBo);                                   \
        const float ggB = fmaf(2.0f, rcpa(1.0f + eBg), -1.0f);                \
        cA = fmaf(gfA, cA, giA * ggA);                                        \
        cB = fmaf(gfB, cB, giB * ggB);                                        \
        const float tcA = ex2a(NEG2 * cA);                                    \
        const float tcB = ex2a(NEG2 * cB);                                    \
        const float hvA = goA * fmaf(2.0f, rcpa(1.0f + tcA), -1.0f);          \
        const float hvB = goB * fmaf(2.0f, rcpa(1.0f + tcB), -1.0f);          \
        if (lane < HH) { sts32((WA_A) + sl, hvA); sts32((WA_B) + sl, hvB); }  \
        /* no __syncwarp: warp-private smem, in-order per-warp LSU */         \
    }

#pragma unroll 1
    for (int tb = 0; tb < TT / 2; tb++) {
        const int tn = (tb + 1 < TT / 2) ? tb + 1 : tb;
        float2 xnA = xpA[tn], xnB = xpB[tn];
        STEP(aP0A, aP0B, aP1A, aP1B, xqA.x, xqB.x, (tb > 0), 2 * tb)
        STEP(aP1A, aP1B, aP0A, aP0B, xqA.y, xqB.y, true,     2 * tb + 1)
        xqA = xnA; xqB = xnB;
    }
#undef STEP

    // tail: one more broadcast round for y[T-1] (final h is in ping 0)
    __syncwarp();
    {
        u64 dA = fmul2(lds64(aP0A), Wd[0]);
        u64 dB = fmul2(lds64(aP0B), Wd[0]);
#pragma unroll
        for (int p = 1; p < NPAIR; p++) {
            dA = ffma2(lds64(aP0A + 8u * p), Wd[p], dA);
            dB = ffma2(lds64(aP0B + 8u * p), Wd[p], dB);
        }
        if (lane == 0) {
            oA[TT - 1] = lo2(dA) + hi2(dA);
            oB[TT - 1] = lo2(dB) + hi2(dB);
        }
    }
}

extern "C" void kernel_launch(void* const* d_in, const int* in_sizes, int n_in,
                              void* d_out, int out_size) {
    const float* x       = (const float*)d_in[0];
    const float* w_ih    = (const float*)d_in[1];
    const float* w_hh    = (const float*)d_in[2];
    const float* b_ih    = (const float*)d_in[3];
    const float* b_hh    = (const float*)d_in[4];
    const float* w_dense = (const float*)d_in[5];
    const float* b_dense = (const float*)d_in[6];
    float* out = (float*)d_out;

    // 1024 CTAs x 32 threads: one warp per CTA, two sequences per warp.
    lstm_x2<<<BATCH / 2, 32>>>(x, w_ih, w_hh, b_ih, b_hh,
                               w_dense, b_dense, out);
}

// round 13
// speedup vs baseline: 1.2897x; 1.0784x over previous
#include <cuda_runtime.h>

#define BATCH 2048
#define TT    2048
#define HH    25

typedef unsigned long long u64;

// Packed f32x2 ops (Blackwell, PTX-only): two fp32 FMAs/MULs per instruction.
__device__ __forceinline__ u64 ffma2(u64 a, u64 b, u64 c) {
    u64 d; asm("fma.rn.f32x2 %0, %1, %2, %3;" : "=l"(d) : "l"(a), "l"(b), "l"(c)); return d;
}
__device__ __forceinline__ u64 fmul2(u64 a, u64 b) {
    u64 d; asm("mul.rn.f32x2 %0, %1, %2;" : "=l"(d) : "l"(a), "l"(b)); return d;
}
__device__ __forceinline__ u64 pk2(float lo, float hi) {
    u64 r; asm("mov.b64 %0, {%1, %2};" : "=l"(r) : "f"(lo), "f"(hi)); return r;
}
__device__ __forceinline__ float lo2(u64 a) { return __uint_as_float((unsigned)a); }
__device__ __forceinline__ float hi2(u64 a) { return __uint_as_float((unsigned)(a >> 32)); }

__device__ __forceinline__ float ex2a(float x) { float r; asm("ex2.approx.f32 %0, %1;" : "=f"(r) : "f"(x)); return r; }
__device__ __forceinline__ float rcpa(float x) { float r; asm("rcp.approx.f32 %0, %1;" : "=f"(r) : "f"(x)); return r; }

__device__ __forceinline__ u64 lds64(unsigned a) {
    u64 r; asm volatile("ld.shared.b64 %0, [%1];" : "=l"(r) : "r"(a) : "memory"); return r;
}
__device__ __forceinline__ void lds128(unsigned a, u64& p0, u64& p1) {
    asm volatile("ld.shared.v2.u64 {%0, %1}, [%2];" : "=l"(p0), "=l"(p1) : "r"(a) : "memory");
}
__device__ __forceinline__ float4 lds128f(unsigned a) {
    float4 r;
    asm volatile("ld.shared.v4.f32 {%0, %1, %2, %3}, [%4];"
                 : "=f"(r.x), "=f"(r.y), "=f"(r.z), "=f"(r.w) : "r"(a) : "memory");
    return r;
}
__device__ __forceinline__ void sts32(unsigned a, float v) {
    asm volatile("st.shared.f32 [%0], %1;" :: "r"(a), "f"(v) : "memory");
}

#define LOG2E 1.44269504088896340736f
#define NEG1  (-LOG2E)
#define NEG2  (-2.0f * LOG2E)

// Row-redistributed dual-sequence LSTM. 101 dot-rows (100 gate rows laid out
// as row = 4*unit + gate, plus row 100 = dense head) spread over all 32 lanes:
// lane L, slot s owns row 32s+L -> only 4 packed dots per lane per seq-step
// (vs 5 with 7 idle lanes before). Row weights/bias/u are PRESCALED by -log2e
// (sigmoid rows) or -2log2e (tanh row g==2) so every row's activation is the
// uniform v = fma(a, rcp(1+ex2(arg)), b), (a,b)=(1,0) or (2,-1). Bias rides in
// weight-pair-12's hi slot against the const-1.0 kept in h slot 25.
// The dense row's RAW dot (unscaled, bias folded) is y[t-1] itself, stored by
// lane 4 -- no reduction, no extra dot. Activated gates hop through smem:
// 4 conflict-free STS.32 per lane, then unit j's gates (i,f,g,o) come back as
// ONE aligned LDS.128 for the state update. Cross-lane smem visibility inside
// one warp needs no syncwarp (in-order per-warp LSU; validated in R10).
__global__ void __launch_bounds__(32, 7)
lstm_rr(const float* __restrict__ x,        // [B, T, 1]
        const float* __restrict__ w_ih,     // [4H, 1]
        const float* __restrict__ w_hh,     // [4H, H]
        const float* __restrict__ b_ih,     // [4H]
        const float* __restrict__ b_hh,     // [4H]
        const float* __restrict__ w_dense,  // [1, H]
        const float* __restrict__ b_dense,  // [1]
        float* __restrict__ out)            // [B, T, 1]
{
    // bytes: [0,128) hA ping0 | [128,256) hA ping1 | [256,768) gatesA(128f)
    //        [768,896) hB p0  | [896,1024) hB p1   | [1024,1536) gatesB
    __shared__ __align__(16) float sm[384];

    const int lane = (int)(threadIdx.x & 31u);
    const int seqA = blockIdx.x * 2;

    // ---- per-lane row config: 4 slots, row = 32s + lane ----
    u64 Wr[4][13];
    float nU[4], aAct[4], bAct[4];
#pragma unroll
    for (int s = 0; s < 4; s++) {
        const int r = 32 * s + lane;
        if (r < 100) {
            const int g = r & 3, u = r >> 2;
            const float sc = (g == 2) ? NEG2 : NEG1;
            const float* row = w_hh + (g * HH + u) * HH;
#pragma unroll
            for (int p = 0; p < 12; p++)
                Wr[s][p] = pk2(sc * row[2 * p], sc * row[2 * p + 1]);
            Wr[s][12] = pk2(sc * row[24],
                            sc * (b_ih[g * HH + u] + b_hh[g * HH + u]));
            nU[s]   = sc * w_ih[g * HH + u];
            aAct[s] = (g == 2) ? 2.0f : 1.0f;
            bAct[s] = (g == 2) ? -1.0f : 0.0f;
        } else if (r == 100) {                      // dense head (lane 4, s=3)
#pragma unroll
            for (int p = 0; p < 12; p++)
                Wr[s][p] = pk2(w_dense[2 * p], w_dense[2 * p + 1]);
            Wr[s][12] = pk2(w_dense[24], b_dense[0]);
            nU[s] = 0.0f; aAct[s] = 0.0f; bAct[s] = 0.0f;
        } else {                                    // padding rows 101..127
#pragma unroll
            for (int p = 0; p < 13; p++) Wr[s][p] = 0ull;
            nU[s] = 0.0f; aAct[s] = 0.0f; bAct[s] = 0.0f;
        }
    }

    const float2* xpA = reinterpret_cast<const float2*>(x + (size_t)seqA * TT);
    const float2* xpB = reinterpret_cast<const float2*>(x + (size_t)(seqA + 1) * TT);
    float* oA = out + (size_t)seqA * TT;
    float* oB = out + (size_t)(seqA + 1) * TT;

    const unsigned base = (unsigned)__cvta_generic_to_shared(sm);
    const unsigned hA0 = base,         hA1 = base + 128u, gA = base + 256u;
    const unsigned hB0 = base + 768u,  hB1 = base + 896u, gB = base + 1024u;
    const unsigned sgA = gA + 4u * (unsigned)lane;   // gate stores (+128*s)
    const unsigned sgB = gB + 4u * (unsigned)lane;
    const int jj = (lane < HH) ? lane : 0;           // state unit (clamped)
    const unsigned stA = gA + 16u * (unsigned)jj;    // state gathers (f4-aligned)
    const unsigned stB = gB + 16u * (unsigned)jj;
    const unsigned shl = 4u * (unsigned)lane;        // h store offset

    // init all four h buffers: h=0, slot 25 = 1.0 (permanent bias feed)
    {
        const float v = (lane == HH) ? 1.0f : 0.0f;
        sm[0 + lane] = v;   sm[32 + lane] = v;        // hA p0, p1
        sm[192 + lane] = v; sm[224 + lane] = v;       // hB p0, p1
    }
    __syncwarp();

    float cA = 0.0f, cB = 0.0f;
    float2 xqA = xpA[0], xqB = xpB[0];

    // One step for both sequences. HRA/HRB: h read bufs (hold h[t-1]);
    // HWA/HWB: h write bufs; XA/XB: x[t]; stores y[t-1] when STORE0.
#define STEP(HRA, HRB, HWA, HWB, XA, XB, STORE0, GT)                          \
    {                                                                         \
        u64 pa0, pa1, pa2, pa3, pa4, pa5, pa6, pa7, pa8, pa9, pa10, pa11;     \
        u64 pb0, pb1, pb2, pb3, pb4, pb5, pb6, pb7, pb8, pb9, pb10, pb11;     \
        lds128((HRA) +  0u, pa0, pa1);   lds128((HRB) +  0u, pb0, pb1);       \
        lds128((HRA) + 16u, pa2, pa3);   lds128((HRB) + 16u, pb2, pb3);       \
        lds128((HRA) + 32u, pa4, pa5);   lds128((HRB) + 32u, pb4, pb5);       \
        lds128((HRA) + 48u, pa6, pa7);   lds128((HRB) + 48u, pb6, pb7);       \
        lds128((HRA) + 64u, pa8, pa9);   lds128((HRB) + 64u, pb8, pb9);       \
        lds128((HRA) + 80u, pa10, pa11); lds128((HRB) + 80u, pb10, pb11);     \
        const u64 pa12 = lds64((HRA) + 96u);                                  \
        const u64 pb12 = lds64((HRB) + 96u);                                  \
        u64 A0 = fmul2(pa0, Wr[0][0]);   u64 B0 = fmul2(pb0, Wr[0][0]);       \
        u64 A1 = fmul2(pa0, Wr[1][0]);   u64 B1 = fmul2(pb0, Wr[1][0]);       \
        u64 A2 = fmul2(pa0, Wr[2][0]);   u64 B2 = fmul2(pb0, Wr[2][0]);       \
        u64 A3 = fmul2(pa0, Wr[3][0]);   u64 B3 = fmul2(pb0, Wr[3][0]);       \
        _Pragma("unroll")                                                     \
        for (int p = 1; p < 13; p++) {                                        \
            const u64 ha = (p==1)?pa1:(p==2)?pa2:(p==3)?pa3:(p==4)?pa4:       \
                           (p==5)?pa5:(p==6)?pa6:(p==7)?pa7:(p==8)?pa8:       \
                           (p==9)?pa9:(p==10)?pa10:(p==11)?pa11:pa12;         \
            const u64 hb = (p==1)?pb1:(p==2)?pb2:(p==3)?pb3:(p==4)?pb4:       \
                           (p==5)?pb5:(p==6)?pb6:(p==7)?pb7:(p==8)?pb8:       \
                           (p==9)?pb9:(p==10)?pb10:(p==11)?pb11:pb12;         \
            A0 = ffma2(ha, Wr[0][p], A0);  B0 = ffma2(hb, Wr[0][p], B0);      \
            A1 = ffma2(ha, Wr[1][p], A1);  B1 = ffma2(hb, Wr[1][p], B1);      \
            A2 = ffma2(ha, Wr[2][p], A2);  B2 = ffma2(hb, Wr[2][p], B2);      \
            A3 = ffma2(ha, Wr[3][p], A3);  B3 = ffma2(hb, Wr[3][p], B3);      \
        }                                                                     \
        const float aA0 = fmaf((XA), nU[0], lo2(A0) + hi2(A0));               \
        const float aA1 = fmaf((XA), nU[1], lo2(A1) + hi2(A1));               \
        const float aA2 = fmaf((XA), nU[2], lo2(A2) + hi2(A2));               \
        const float aA3 = fmaf((XA), nU[3], lo2(A3) + hi2(A3));               \
        const float aB0 = fmaf((XB), nU[0], lo2(B0) + hi2(B0));               \
        const float aB1 = fmaf((XB), nU[1], lo2(B1) + hi2(B1));               \
        const float aB2 = fmaf((XB), nU[2], lo2(B2) + hi2(B2));               \
        const float aB3 = fmaf((XB), nU[3], lo2(B3) + hi2(B3));               \
        /* dense: lane 4 slot 3 raw dot == y[t-1] (bias folded, nU=0) */      \
        if ((STORE0) && lane == 4) {                                          \
            oA[(GT) - 1] = aA3;  oB[(GT) - 1] = aB3;                          \
        }                                                                     \
        const float eA0 = ex2a(aA0), eA1 = ex2a(aA1);                         \
        const float eA2 = ex2a(aA2), eA3 = ex2a(aA3);                         \
        const float eB0 = ex2a(aB0), eB1 = ex2a(aB1);                         \
        const float eB2 = ex2a(aB2), eB3 = ex2a(aB3);                         \
        const float vA0 = fmaf(aAct[0], rcpa(1.0f + eA0), bAct[0]);           \
        const float vA1 = fmaf(aAct[1], rcpa(1.0f + eA1), bAct[1]);           \
        const float vA2 = fmaf(aAct[2], rcpa(1.0f + eA2), bAct[2]);           \
        const float vA3 = fmaf(aAct[3], rcpa(1.0f + eA3), bAct[3]);           \
        const float vB0 = fmaf(aAct[0], rcpa(1.0f + eB0), bAct[0]);           \
        const float vB1 = fmaf(aAct[1], rcpa(1.0f + eB1), bAct[1]);           \
        const float vB2 = fmaf(aAct[2], rcpa(1.0f + eB2), bAct[2]);           \
        const float vB3 = fmaf(aAct[3], rcpa(1.0f + eB3), bAct[3]);           \
        sts32(sgA +   0u, vA0); sts32(sgA + 128u, vA1);                       \
        sts32(sgA + 256u, vA2); sts32(sgA + 384u, vA3);                       \
        sts32(sgB +   0u, vB0); sts32(sgB + 128u, vB1);                       \
        sts32(sgB + 256u, vB2); sts32(sgB + 384u, vB3);                       \
        /* state: gather (i,f,g,o) of unit jj as one float4 */                \
        const float4 qA = lds128f(stA);                                       \
        const float4 qB = lds128f(stB);                                       \
        cA = fmaf(qA.y, cA, qA.x * qA.z);                                     \
        cB = fmaf(qB.y, cB, qB.x * qB.z);                                     \
        const float tA = ex2a(NEG2 * cA);                                     \
        const float tB = ex2a(NEG2 * cB);                                     \
        const float hvA = qA.w * fmaf(2.0f, rcpa(1.0f + tA), -1.0f);          \
        const float hvB = qB.w * fmaf(2.0f, rcpa(1.0f + tB), -1.0f);          \
        if (lane < HH) { sts32((HWA) + shl, hvA); sts32((HWB) + shl, hvB); }  \
    }

#pragma unroll 1
    for (int tb = 0; tb < TT / 2; tb++) {
        const int tn = (tb + 1 < TT / 2) ? tb + 1 : tb;
        float2 xnA = xpA[tn], xnB = xpB[tn];
        STEP(hA0, hB0, hA1, hB1, xqA.x, xqB.x, (tb > 0), 2 * tb)
        STEP(hA1, hB1, hA0, hB0, xqA.y, xqB.y, true,     2 * tb + 1)
        xqA = xnA; xqB = xnB;
    }
#undef STEP

    // tail: y[T-1] from final h (in ping 0) via the dense row (lane 4, Wr[3])
    {
        u64 pa0, pa1, pa2, pa3, pa4, pa5, pa6, pa7, pa8, pa9, pa10, pa11;
        u64 pb0, pb1, pb2, pb3, pb4, pb5, pb6, pb7, pb8, pb9, pb10, pb11;
        lds128(hA0 +  0u, pa0, pa1);   lds128(hB0 +  0u, pb0, pb1);
        lds128(hA0 + 16u, pa2, pa3);   lds128(hB0 + 16u, pb2, pb3);
        lds128(hA0 + 32u, pa4, pa5);   lds128(hB0 + 32u, pb4, pb5);
        lds128(hA0 + 48u, pa6, pa7);   lds128(hB0 + 48u, pb6, pb7);
        lds128(hA0 + 64u, pa8, pa9);   lds128(hB0 + 64u, pb8, pb9);
        lds128(hA0 + 80u, pa10, pa11); lds128(hB0 + 80u, pb10, pb11);
        const u64 pa12 = lds64(hA0 + 96u);
        const u64 pb12 = lds64(hB0 + 96u);
        u64 dA = fmul2(pa0, Wr[3][0]);
        u64 dB = fmul2(pb0, Wr[3][0]);
        dA = ffma2(pa1, Wr[3][1], dA);   dB = ffma2(pb1, Wr[3][1], dB);
        dA = ffma2(pa2, Wr[3][2], dA);   dB = ffma2(pb2, Wr[3][2], dB);
        dA = ffma2(pa3, Wr[3][3], dA);   dB = ffma2(pb3, Wr[3][3], dB);
        dA = ffma2(pa4, Wr[3][4], dA);   dB = ffma2(pb4, Wr[3][4], dB);
        dA = ffma2(pa5, Wr[3][5], dA);   dB = ffma2(pb5, Wr[3][5], dB);
        dA = ffma2(pa6, Wr[3][6], dA);   dB = ffma2(pb6, Wr[3][6], dB);
        dA = ffma2(pa7, Wr[3][7], dA);   dB = ffma2(pb7, Wr[3][7], dB);
        dA = ffma2(pa8, Wr[3][8], dA);   dB = ffma2(pb8, Wr[3][8], dB);
        dA = ffma2(pa9, Wr[3][9], dA);   dB = ffma2(pb9, Wr[3][9], dB);
        dA = ffma2(pa10, Wr[3][10], dA); dB = ffma2(pb10, Wr[3][10], dB);
        dA = ffma2(pa11, Wr[3][11], dA); dB = ffma2(pb11, Wr[3][11], dB);
        dA = ffma2(pa12, Wr[3][12], dA); dB = ffma2(pb12, Wr[3][12], dB);
        if (lane == 4) {
            oA[TT - 1] = lo2(dA) + hi2(dA);
            oB[TT - 1] = lo2(dB) + hi2(dB);
        }
    }
}

extern "C" void kernel_launch(void* const* d_in, const int* in_sizes, int n_in,
                              void* d_out, int out_size) {
    const float* x       = (const float*)d_in[0];
    const float* w_ih    = (const float*)d_in[1];
    const float* w_hh    = (const float*)d_in[2];
    const float* b_ih    = (const float*)d_in[3];
    const float* b_hh    = (const float*)d_in[4];
    const float* w_dense = (const float*)d_in[5];
    const float* b_dense = (const float*)d_in[6];
    float* out = (float*)d_out;

    // 1024 CTAs x 32 threads: one warp per CTA, two sequences per warp,
    // all 32 lanes productive (101 dot-rows over 4 slots).
    lstm_rr<<<BATCH / 2, 32>>>(x, w_ih, w_hh, b_ih, b_hh,
                               w_dense, b_dense, out);
}

// round 14
// speedup vs baseline: 1.6624x; 1.2890x over previous
#include <cuda_runtime.h>

#define BATCH 2048
#define TT    2048
#define HH    25

typedef unsigned long long u64;

// Packed f32x2 ops (Blackwell, PTX-only): two fp32 FMAs/MULs per instruction.
__device__ __forceinline__ u64 ffma2(u64 a, u64 b, u64 c) {
    u64 d; asm("fma.rn.f32x2 %0, %1, %2, %3;" : "=l"(d) : "l"(a), "l"(b), "l"(c)); return d;
}
__device__ __forceinline__ u64 fmul2(u64 a, u64 b) {
    u64 d; asm("mul.rn.f32x2 %0, %1, %2;" : "=l"(d) : "l"(a), "l"(b)); return d;
}
__device__ __forceinline__ u64 pk2(float lo, float hi) {
    u64 r; asm("mov.b64 %0, {%1, %2};" : "=l"(r) : "f"(lo), "f"(hi)); return r;
}
__device__ __forceinline__ float lo2(u64 a) { return __uint_as_float((unsigned)a); }
__device__ __forceinline__ float hi2(u64 a) { return __uint_as_float((unsigned)(a >> 32)); }

// MUFU.TANH: single-instruction tanh (sm_75+; the RNN-activation unit).
__device__ __forceinline__ float tanha(float x) {
    float r; asm("tanh.approx.f32 %0, %1;" : "=f"(r) : "f"(x)); return r;
}

__device__ __forceinline__ u64 lds64(unsigned a) {
    u64 r; asm volatile("ld.shared.b64 %0, [%1];" : "=l"(r) : "r"(a) : "memory"); return r;
}
__device__ __forceinline__ void lds128(unsigned a, u64& p0, u64& p1) {
    asm volatile("ld.shared.v2.u64 {%0, %1}, [%2];" : "=l"(p0), "=l"(p1) : "r"(a) : "memory");
}
__device__ __forceinline__ float4 lds128f(unsigned a) {
    float4 r;
    asm volatile("ld.shared.v4.f32 {%0, %1, %2, %3}, [%4];"
                 : "=f"(r.x), "=f"(r.y), "=f"(r.z), "=f"(r.w) : "r"(a) : "memory");
    return r;
}
__device__ __forceinline__ void sts32(unsigned a, float v) {
    asm volatile("st.shared.f32 [%0], %1;" :: "r"(a), "f"(v) : "memory");
}

// Row-redistributed dual-sequence LSTM with MUFU.TANH activations.
// 101 dot-rows (row = 4*unit + gate, row 100 = dense head) spread over all 32
// lanes: lane L, slot s owns row 32s+L -> 4 packed dots per lane per seq-step.
// ALL activations via one tanh.approx each, using sigmoid(z) = 0.5 + 0.5*
// tanh(z/2): sigmoid rows are PRESCALED by 0.5 (weights+bias+u), tanh row
// (g==2) by 1.0, so every row is v = fma(a, tanh(arg), b), (a,b) = (0.5,0.5)
// or (1,0). tanh(c) on the critical c->h path is also a single MUFU.
// Dense row's raw dot (unscaled, bias folded via const-1.0 h slot 25) is
// y[t-1] directly, stored by lane 4. Activated gates hop through smem
// (4 conflict-free STS.32, one aligned LDS.128 gather per unit). Warp-private
// smem, in-order per-warp LSU -> no syncwarp in the loop (validated R10).
__global__ void __launch_bounds__(32, 7)
lstm_rr(const float* __restrict__ x,        // [B, T, 1]
        const float* __restrict__ w_ih,     // [4H, 1]
        const float* __restrict__ w_hh,     // [4H, H]
        const float* __restrict__ b_ih,     // [4H]
        const float* __restrict__ b_hh,     // [4H]
        const float* __restrict__ w_dense,  // [1, H]
        const float* __restrict__ b_dense,  // [1]
        float* __restrict__ out)            // [B, T, 1]
{
    // bytes: [0,128) hA p0 | [128,256) hA p1 | [256,768) gatesA (128 f32)
    //        [768,896) hB p0 | [896,1024) hB p1 | [1024,1536) gatesB
    __shared__ __align__(16) float sm[384];

    const int lane = (int)(threadIdx.x & 31u);
    const int seqA = blockIdx.x * 2;

    // ---- per-lane row config: 4 slots, row = 32s + lane ----
    u64 Wr[4][13];
    float nU[4], aAct[4], bAct[4];
#pragma unroll
    for (int s = 0; s < 4; s++) {
        const int r = 32 * s + lane;
        if (r < 100) {
            const int g = r & 3, u = r >> 2;
            const float sc = (g == 2) ? 1.0f : 0.5f;   // tanh row vs sigmoid rows
            const float* row = w_hh + (g * HH + u) * HH;
#pragma unroll
            for (int p = 0; p < 12; p++)
                Wr[s][p] = pk2(sc * row[2 * p], sc * row[2 * p + 1]);
            Wr[s][12] = pk2(sc * row[24],
                            sc * (b_ih[g * HH + u] + b_hh[g * HH + u]));
            nU[s]   = sc * w_ih[g * HH + u];
            aAct[s] = (g == 2) ? 1.0f : 0.5f;
            bAct[s] = (g == 2) ? 0.0f : 0.5f;
        } else if (r == 100) {                      // dense head (lane 4, s=3)
#pragma unroll
            for (int p = 0; p < 12; p++)
                Wr[s][p] = pk2(w_dense[2 * p], w_dense[2 * p + 1]);
            Wr[s][12] = pk2(w_dense[24], b_dense[0]);
            nU[s] = 0.0f; aAct[s] = 0.0f; bAct[s] = 0.0f;
        } else {                                    // padding rows 101..127
#pragma unroll
            for (int p = 0; p < 13; p++) Wr[s][p] = 0ull;
            nU[s] = 0.0f; aAct[s] = 0.0f; bAct[s] = 0.0f;
        }
    }

    const float2* xpA = reinterpret_cast<const float2*>(x + (size_t)seqA * TT);
    const float2* xpB = reinterpret_cast<const float2*>(x + (size_t)(seqA + 1) * TT);
    float* oA = out + (size_t)seqA * TT;
    float* oB = out + (size_t)(seqA + 1) * TT;

    const unsigned base = (unsigned)__cvta_generic_to_shared(sm);
    const unsigned hA0 = base,         hA1 = base + 128u, gA = base + 256u;
    const unsigned hB0 = base + 768u,  hB1 = base + 896u, gB = base + 1024u;
    const unsigned sgA = gA + 4u * (unsigned)lane;   // gate stores (+128*s)
    const unsigned sgB = gB + 4u * (unsigned)lane;
    const int jj = (lane < HH) ? lane : 0;           // state unit (clamped)
    const unsigned stA = gA + 16u * (unsigned)jj;    // state gathers (f4-aligned)
    const unsigned stB = gB + 16u * (unsigned)jj;
    const unsigned shl = 4u * (unsigned)lane;        // h store offset

    // init all four h buffers: h=0, slot 25 = 1.0 (permanent bias feed)
    {
        const float v = (lane == HH) ? 1.0f : 0.0f;
        sm[0 + lane] = v;   sm[32 + lane] = v;        // hA p0, p1
        sm[192 + lane] = v; sm[224 + lane] = v;       // hB p0, p1
    }
    __syncwarp();

    float cA = 0.0f, cB = 0.0f;
    float2 xqA = xpA[0], xqB = xpB[0];

    // One step for both sequences. HRA/HRB hold h[t-1]; HWA/HWB receive h[t].
#define STEP(HRA, HRB, HWA, HWB, XA, XB, STORE0, GT)                          \
    {                                                                         \
        u64 pa0, pa1, pa2, pa3, pa4, pa5, pa6, pa7, pa8, pa9, pa10, pa11;     \
        u64 pb0, pb1, pb2, pb3, pb4, pb5, pb6, pb7, pb8, pb9, pb10, pb11;     \
        lds128((HRA) +  0u, pa0, pa1);   lds128((HRB) +  0u, pb0, pb1);       \
        lds128((HRA) + 16u, pa2, pa3);   lds128((HRB) + 16u, pb2, pb3);       \
        lds128((HRA) + 32u, pa4, pa5);   lds128((HRB) + 32u, pb4, pb5);       \
        lds128((HRA) + 48u, pa6, pa7);   lds128((HRB) + 48u, pb6, pb7);       \
        lds128((HRA) + 64u, pa8, pa9);   lds128((HRB) + 64u, pb8, pb9);       \
        lds128((HRA) + 80u, pa10, pa11); lds128((HRB) + 80u, pb10, pb11);     \
        const u64 pa12 = lds64((HRA) + 96u);                                  \
        const u64 pb12 = lds64((HRB) + 96u);                                  \
        u64 A0 = fmul2(pa0, Wr[0][0]);   u64 B0 = fmul2(pb0, Wr[0][0]);       \
        u64 A1 = fmul2(pa0, Wr[1][0]);   u64 B1 = fmul2(pb0, Wr[1][0]);       \
        u64 A2 = fmul2(pa0, Wr[2][0]);   u64 B2 = fmul2(pb0, Wr[2][0]);       \
        u64 A3 = fmul2(pa0, Wr[3][0]);   u64 B3 = fmul2(pb0, Wr[3][0]);       \
        _Pragma("unroll")                                                     \
        for (int p = 1; p < 13; p++) {                                        \
            const u64 ha = (p==1)?pa1:(p==2)?pa2:(p==3)?pa3:(p==4)?pa4:       \
                           (p==5)?pa5:(p==6)?pa6:(p==7)?pa7:(p==8)?pa8:       \
                           (p==9)?pa9:(p==10)?pa10:(p==11)?pa11:pa12;         \
            const u64 hb = (p==1)?pb1:(p==2)?pb2:(p==3)?pb3:(p==4)?pb4:       \
                           (p==5)?pb5:(p==6)?pb6:(p==7)?pb7:(p==8)?pb8:       \
                           (p==9)?pb9:(p==10)?pb10:(p==11)?pb11:pb12;         \
            A0 = ffma2(ha, Wr[0][p], A0);  B0 = ffma2(hb, Wr[0][p], B0);      \
            A1 = ffma2(ha, Wr[1][p], A1);  B1 = ffma2(hb, Wr[1][p], B1);      \
            A2 = ffma2(ha, Wr[2][p], A2);  B2 = ffma2(hb, Wr[2][p], B2);      \
            A3 = ffma2(ha, Wr[3][p], A3);  B3 = ffma2(hb, Wr[3][p], B3);      \
        }                                                                     \
        const float aA0 = fmaf((XA), nU[0], lo2(A0) + hi2(A0));               \
        const float aA1 = fmaf((XA), nU[1], lo2(A1) + hi2(A1));               \
        const float aA2 = fmaf((XA), nU[2], lo2(A2) + hi2(A2));               \
        const float aA3 = fmaf((XA), nU[3], lo2(A3) + hi2(A3));               \
        const float aB0 = fmaf((XB), nU[0], lo2(B0) + hi2(B0));               \
        const float aB1 = fmaf((XB), nU[1], lo2(B1) + hi2(B1));               \
        const float aB2 = fmaf((XB), nU[2], lo2(B2) + hi2(B2));               \
        const float aB3 = fmaf((XB), nU[3], lo2(B3) + hi2(B3));               \
        /* dense: lane 4 slot 3 raw dot == y[t-1] (bias folded, nU=0) */      \
        if ((STORE0) && lane == 4) {                                          \
            oA[(GT) - 1] = aA3;  oB[(GT) - 1] = aB3;                          \
        }                                                                     \
        /* uniform activation: v = fma(a, tanh(arg), b) -- one MUFU per row */\
        const float vA0 = fmaf(aAct[0], tanha(aA0), bAct[0]);                 \
        const float vA1 = fmaf(aAct[1], tanha(aA1), bAct[1]);                 \
        const float vA2 = fmaf(aAct[2], tanha(aA2), bAct[2]);                 \
        const float vA3 = fmaf(aAct[3], tanha(aA3), bAct[3]);                 \
        const float vB0 = fmaf(aAct[0], tanha(aB0), bAct[0]);                 \
        const float vB1 = fmaf(aAct[1], tanha(aB1), bAct[1]);                 \
        const float vB2 = fmaf(aAct[2], tanha(aB2), bAct[2]);                 \
        const float vB3 = fmaf(aAct[3], tanha(aB3), bAct[3]);                 \
        sts32(sgA +   0u, vA0); sts32(sgA + 128u, vA1);                       \
        sts32(sgA + 256u, vA2); sts32(sgA + 384u, vA3);                       \
        sts32(sgB +   0u, vB0); sts32(sgB + 128u, vB1);                       \
        sts32(sgB + 256u, vB2); sts32(sgB + 384u, vB3);                       \
        /* state: gather (i,f,g,o) of unit jj as one float4 */                \
        const float4 qA = lds128f(stA);                                       \
        const float4 qB = lds128f(stB);                                       \
        cA = fmaf(qA.y, cA, qA.x * qA.z);                                     \
        cB = fmaf(qB.y, cB, qB.x * qB.z);                                     \
        const float hvA = qA.w * tanha(cA);                                   \
        const float hvB = qB.w * tanha(cB);                                   \
        if (lane < HH) { sts32((HWA) + shl, hvA); sts32((HWB) + shl, hvB); }  \
    }

#pragma unroll 1
    for (int tb = 0; tb < TT / 2; tb++) {
        const int tn = (tb + 1 < TT / 2) ? tb + 1 : tb;
        float2 xnA = xpA[tn], xnB = xpB[tn];
        STEP(hA0, hB0, hA1, hB1, xqA.x, xqB.x, (tb > 0), 2 * tb)
        STEP(hA1, hB1, hA0, hB0, xqA.y, xqB.y, true,     2 * tb + 1)
        xqA = xnA; xqB = xnB;
    }
#undef STEP

    // tail: y[T-1] from final h (in ping 0) via the dense row (slot 3 weights)
    __syncwarp();
    {
        u64 pa0, pa1, pa2, pa3, pa4, pa5, pa6, pa7, pa8, pa9, pa10, pa11;
        u64 pb0, pb1, pb2, pb3, pb4, pb5, pb6, pb7, pb8, pb9, pb10, pb11;
        lds128(hA0 +  0u, pa0, pa1);   lds128(hB0 +  0u, pb0, pb1);
        lds128(hA0 + 16u, pa2, pa3);   lds128(hB0 + 16u, pb2, pb3);
        lds128(hA0 + 32u, pa4, pa5);   lds128(hB0 + 32u, pb4, pb5);
        lds128(hA0 + 48u, pa6, pa7);   lds128(hB0 + 48u, pb6, pb7);
        lds128(hA0 + 64u, pa8, pa9);   lds128(hB0 + 64u, pb8, pb9);
        lds128(hA0 + 80u, pa10, pa11); lds128(hB0 + 80u, pb10, pb11);
        const u64 pa12 = lds64(hA0 + 96u);
        const u64 pb12 = lds64(hB0 + 96u);
        u64 dA = fmul2(pa0, Wr[3][0]);
        u64 dB = fmul2(pb0, Wr[3][0]);
        dA = ffma2(pa1, Wr[3][1], dA);   dB = ffma2(pb1, Wr[3][1], dB);
        dA = ffma2(pa2, Wr[3][2], dA);   dB = ffma2(pb2, Wr[3][2], dB);
        dA = ffma2(pa3, Wr[3][3], dA);   dB = ffma2(pb3, Wr[3][3], dB);
        dA = ffma2(pa4, Wr[3][4], dA);   dB = ffma2(pb4, Wr[3][4], dB);
        dA = ffma2(pa5, Wr[3][5], dA);   dB = ffma2(pb5, Wr[3][5], dB);
        dA = ffma2(pa6, Wr[3][6], dA);   dB = ffma2(pb6, Wr[3][6], dB);
        dA = ffma2(pa7, Wr[3][7], dA);   dB = ffma2(pb7, Wr[3][7], dB);
        dA = ffma2(pa8, Wr[3][8], dA);   dB = ffma2(pb8, Wr[3][8], dB);
        dA = ffma2(pa9, Wr[3][9], dA);   dB = ffma2(pb9, Wr[3][9], dB);
        dA = ffma2(pa10, Wr[3][10], dA); dB = ffma2(pb10, Wr[3][10], dB);
        dA = ffma2(pa11, Wr[3][11], dA); dB = ffma2(pb11, Wr[3][11], dB);
        dA = ffma2(pa12, Wr[3][12], dA); dB = ffma2(pb12, Wr[3][12], dB);
        if (lane == 4) {
            oA[TT - 1] = lo2(dA) + hi2(dA);
            oB[TT - 1] = lo2(dB) + hi2(dB);
        }
    }
}

extern "C" void kernel_launch(void* const* d_in, const int* in_sizes, int n_in,
                              void* d_out, int out_size) {
    const float* x       = (const float*)d_in[0];
    const float* w_ih    = (const float*)d_in[1];
    const float* w_hh    = (const float*)d_in[2];
    const float* b_ih    = (const float*)d_in[3];
    const float* b_hh    = (const float*)d_in[4];
    const float* w_dense = (const float*)d_in[5];
    const float* b_dense = (const float*)d_in[6];
    float* out = (float*)d_out;

    // 1024 CTAs x 32 threads: one warp per CTA, two sequences per warp,
    // all 32 lanes productive (101 dot-rows over 4 slots).
    lstm_rr<<<BATCH / 2, 32>>>(x, w_ih, w_hh, b_ih, b_hh,
                               w_dense, b_dense, out);
}